// round 16
// baseline (speedup 1.0000x reference)
#include <cuda_runtime.h>

// Problem constants (from reference)
#define S_TOK   131072
#define DIM     512
#define VOCAB   100000
#define K_SLOTS 16        // ranks 0..15 per row; P(count>16) ~ 0 for lambda=0.655

// Scratch (device globals — zero at module load; the update kernel restores the
// all-zero invariant every run, so graph replays are self-consistent).
__device__ int g_counts[VOCAB];          // tokens per vocab row
__device__ int g_slot[VOCAB * K_SLOTS];  // token index per (row, rank). Never needs
                                         // clearing: only ranks < count are read.
__device__ int g_ovf_vidp1[S_TOK];       // overflow sentinel: vid+1 at token pos (0=empty)

// ---------------------------------------------------------------------------
// Kernel 1: histogram + slot placement. 4 tokens per thread via int4 loads
// (4 independent atomic chains per thread, MLP=4). 128-thread blocks -> 256
// blocks spread across all 148 SMs.
// ---------------------------------------------------------------------------
__global__ void compact_kernel(const int4* __restrict__ l2_data4,
                               const int4* __restrict__ l2_idxs4) {
    int i = blockIdx.x * blockDim.x + threadIdx.x;   // i < S_TOK/4
    int4 idx = l2_idxs4[i];
    int4 dat = l2_data4[i];
    int base = i * 4;

    if (idx.x == 1) {
        int r = atomicAdd(&g_counts[dat.x], 1);
        if (r < K_SLOTS) g_slot[dat.x * K_SLOTS + r] = base;
        else             g_ovf_vidp1[base] = dat.x + 1;
    }
    if (idx.y == 1) {
        int r = atomicAdd(&g_counts[dat.y], 1);
        if (r < K_SLOTS) g_slot[dat.y * K_SLOTS + r] = base + 1;
        else             g_ovf_vidp1[base + 1] = dat.y + 1;
    }
    if (idx.z == 1) {
        int r = atomicAdd(&g_counts[dat.z], 1);
        if (r < K_SLOTS) g_slot[dat.z * K_SLOTS + r] = base + 2;
        else             g_ovf_vidp1[base + 2] = dat.z + 1;
    }
    if (idx.w == 1) {
        int r = atomicAdd(&g_counts[dat.w], 1);
        if (r < K_SLOTS) g_slot[dat.w * K_SLOTS + r] = base + 3;
        else             g_ovf_vidp1[base + 3] = dat.w + 1;
    }
}

// ---------------------------------------------------------------------------
// Per-row tail: given preloaded w registers and the row's count, finish the
// row (copy or gather+EMA). Inlined; cold overflow branch kept inside.
// ---------------------------------------------------------------------------
__device__ __forceinline__ void finish_row(
    int row, int c, long base, int lane,
    float4 w0, float4 w1, float4 w2, float4 w3,
    const float4* __restrict__ x4, float4* __restrict__ out4) {

    if (c == 0) {
        __stcs(&out4[base + lane],      w0);
        __stcs(&out4[base + lane + 32], w1);
        __stcs(&out4[base + lane + 64], w2);
        __stcs(&out4[base + lane + 96], w3);
        return;
    }

    // --- gather ranks 0..min(c,K)-1 ---
    float4 s0 = make_float4(0.f, 0.f, 0.f, 0.f);
    float4 s1 = s0, s2 = s0, s3 = s0;

    int ns = (c < K_SLOTS) ? c : K_SLOTS;
    for (int t = 0; t < ns; t++) {
        int tok = g_slot[row * K_SLOTS + t];          // warp-uniform broadcast
        const float4* src = x4 + (long)tok * (DIM / 4);
        float4 a = __ldcs(&src[lane]);
        float4 b = __ldcs(&src[lane + 32]);
        float4 d = __ldcs(&src[lane + 64]);
        float4 e = __ldcs(&src[lane + 96]);
        s0.x += a.x; s0.y += a.y; s0.z += a.z; s0.w += a.w;
        s1.x += b.x; s1.y += b.y; s1.z += b.z; s1.w += b.w;
        s2.x += d.x; s2.y += d.y; s2.z += d.z; s2.w += d.w;
        s3.x += e.x; s3.y += e.y; s3.z += e.z; s3.w += e.w;
    }

    if (c > K_SLOTS) {
        // cold overflow path: correct for any input, never taken for this data
        int remaining = c - K_SLOTS;
        for (int b0 = 0; b0 < S_TOK && remaining > 0; b0 += 32) {
            int vpo = g_ovf_vidp1[b0 + lane];
            unsigned m = __ballot_sync(0xFFFFFFFFu, vpo == row + 1);
            while (m) {
                int j2 = b0 + (__ffs(m) - 1);
                m &= m - 1;
                const float4* src = x4 + (long)j2 * (DIM / 4);
                float4 a = src[lane];
                float4 b = src[lane + 32];
                float4 d = src[lane + 64];
                float4 e = src[lane + 96];
                s0.x += a.x; s0.y += a.y; s0.z += a.z; s0.w += a.w;
                s1.x += b.x; s1.y += b.y; s1.z += b.z; s1.w += b.w;
                s2.x += d.x; s2.y += d.y; s2.z += d.z; s2.w += d.w;
                s3.x += e.x; s3.y += e.y; s3.z += e.z; s3.w += e.w;
                if (lane == 0) g_ovf_vidp1[j2] = 0;   // consume + clear
                remaining--;
            }
        }
    }

    // --- final EMA write ---
    float inv = 0.5f / (float)c;
    __stcs(&out4[base + lane], make_float4(
        fmaf(s0.x, inv, 0.5f * w0.x), fmaf(s0.y, inv, 0.5f * w0.y),
        fmaf(s0.z, inv, 0.5f * w0.z), fmaf(s0.w, inv, 0.5f * w0.w)));
    __stcs(&out4[base + lane + 32], make_float4(
        fmaf(s1.x, inv, 0.5f * w1.x), fmaf(s1.y, inv, 0.5f * w1.y),
        fmaf(s1.z, inv, 0.5f * w1.z), fmaf(s1.w, inv, 0.5f * w1.w)));
    __stcs(&out4[base + lane + 64], make_float4(
        fmaf(s2.x, inv, 0.5f * w2.x), fmaf(s2.y, inv, 0.5f * w2.y),
        fmaf(s2.z, inv, 0.5f * w2.z), fmaf(s2.w, inv, 0.5f * w2.w)));
    __stcs(&out4[base + lane + 96], make_float4(
        fmaf(s3.x, inv, 0.5f * w3.x), fmaf(s3.y, inv, 0.5f * w3.y),
        fmaf(s3.z, inv, 0.5f * w3.z), fmaf(s3.w, inv, 0.5f * w3.w)));
}

// ---------------------------------------------------------------------------
// Kernel 2: update, ROW-PAIR version. One warp owns two adjacent vocab rows.
// The w reads for BOTH rows are issued up front — 8 independent line loads
// per thread on every path (w is needed unconditionally), doubling front-end
// MLP vs R13's 4. Counts are loaded first (2 independent loads), then both
// w streams fill while counts resolve. No reg cap: R14 proved capping regs
// serializes per-thread loads and loses more than occupancy gains.
// Grid: VOCAB/2 pairs / 8 warps = 6250 blocks of 256, exact coverage.
// Scratch reset folded in race-free (each warp owns its rows' counts).
// ---------------------------------------------------------------------------
__global__ void __launch_bounds__(256)
update_kernel(const float4* __restrict__ x4,
              const float4* __restrict__ w4,
              float4* __restrict__ out4) {
    int pair = (blockIdx.x * blockDim.x + threadIdx.x) >> 5;
    int lane = threadIdx.x & 31;
    int r0 = pair * 2;
    int r1 = r0 + 1;

    int c0 = g_counts[r0];                 // two independent count loads
    int c1 = g_counts[r1];

    long b0 = (long)r0 * (DIM / 4);
    long b1 = (long)r1 * (DIM / 4);

    // Front-load w for both rows: 8 independent loads in flight per thread.
    float4 w00 = __ldcs(&w4[b0 + lane]);
    float4 w01 = __ldcs(&w4[b0 + lane + 32]);
    float4 w02 = __ldcs(&w4[b0 + lane + 64]);
    float4 w03 = __ldcs(&w4[b0 + lane + 96]);
    float4 w10 = __ldcs(&w4[b1 + lane]);
    float4 w11 = __ldcs(&w4[b1 + lane + 32]);
    float4 w12 = __ldcs(&w4[b1 + lane + 64]);
    float4 w13 = __ldcs(&w4[b1 + lane + 96]);

    if (lane == 0) {                       // reset for next replay
        if (c0 != 0) g_counts[r0] = 0;
        if (c1 != 0) g_counts[r1] = 0;
    }

    finish_row(r0, c0, b0, lane, w00, w01, w02, w03, x4, out4);
    finish_row(r1, c1, b1, lane, w10, w11, w12, w13, x4, out4);
}

// ---------------------------------------------------------------------------
extern "C" void kernel_launch(void* const* d_in, const int* in_sizes, int n_in,
                              void* d_out, int out_size) {
    const float* out_act   = (const float*)d_in[0];   // [S, D] f32
    const float* l2_weight = (const float*)d_in[1];   // [V, D] f32
    const int*   l2_data   = (const int*)d_in[2];     // [S] i32
    const int*   l2_idxs   = (const int*)d_in[3];     // [S] i32
    float* outp = (float*)d_out;                      // [V, D] f32

    (void)in_sizes; (void)n_in; (void)out_size;

    // 1. histogram + slots (scratch all-zero on entry; 4 tokens/thread,
    //    128-thread blocks -> 256 blocks across 148 SMs)
    compact_kernel<<<S_TOK / 4 / 128, 128>>>((const int4*)l2_data,
                                             (const int4*)l2_idxs);

    // 2. update: row-pair per warp, front-loaded w (8-deep MLP), exact grid
    update_kernel<<<VOCAB / 16, 256>>>((const float4*)out_act,
                                       (const float4*)l2_weight,
                                       (float4*)outp);
}

// round 17
// speedup vs baseline: 1.0987x; 1.0987x over previous
#include <cuda_runtime.h>

// Problem constants (from reference)
#define S_TOK   131072
#define DIM     512
#define VOCAB   100000
#define K_SLOTS 16        // ranks 0..15 per row; P(count>16) ~ 0 for lambda=0.655

// Scratch (device globals — zero at module load; the update kernel restores the
// all-zero invariant every run, so graph replays are self-consistent).
__device__ int g_counts[VOCAB];          // tokens per vocab row
__device__ int g_slot[VOCAB * K_SLOTS];  // token index per (row, rank). Never needs
                                         // clearing: only ranks < count are read.
__device__ int g_ovf_vidp1[S_TOK];       // overflow sentinel: vid+1 at token pos (0=empty)

// ---------------------------------------------------------------------------
// Kernel 1: histogram + slot placement. 4 tokens per thread via int4 loads
// (4 independent atomic chains per thread, MLP=4). 128-thread blocks so the
// grid is 256 blocks — ~2 per SM across 148 SMs.
// ---------------------------------------------------------------------------
__global__ void compact_kernel(const int4* __restrict__ l2_data4,
                               const int4* __restrict__ l2_idxs4) {
    int i = blockIdx.x * blockDim.x + threadIdx.x;   // i < S_TOK/4
    int4 idx = l2_idxs4[i];
    int4 dat = l2_data4[i];
    int base = i * 4;

    if (idx.x == 1) {
        int r = atomicAdd(&g_counts[dat.x], 1);
        if (r < K_SLOTS) g_slot[dat.x * K_SLOTS + r] = base;
        else             g_ovf_vidp1[base] = dat.x + 1;
    }
    if (idx.y == 1) {
        int r = atomicAdd(&g_counts[dat.y], 1);
        if (r < K_SLOTS) g_slot[dat.y * K_SLOTS + r] = base + 1;
        else             g_ovf_vidp1[base + 1] = dat.y + 1;
    }
    if (idx.z == 1) {
        int r = atomicAdd(&g_counts[dat.z], 1);
        if (r < K_SLOTS) g_slot[dat.z * K_SLOTS + r] = base + 2;
        else             g_ovf_vidp1[base + 2] = dat.z + 1;
    }
    if (idx.w == 1) {
        int r = atomicAdd(&g_counts[dat.w], 1);
        if (r < K_SLOTS) g_slot[dat.w * K_SLOTS + r] = base + 3;
        else             g_ovf_vidp1[base + 3] = dat.w + 1;
    }
}

// ---------------------------------------------------------------------------
// Kernel 2: update (R13 exact — converged optimum: 83.9-85.1us kernel,
// 89.5-90.2us total across three reproductions).
// Warp-per-row over ALL rows (exact grid: VOCAB/8 blocks of 256).
//   c==0 -> out = w (streaming copy; 52% of rows — saturates DRAM and hides
//           the gather warps' dependent-load latency)
//   c>=1 -> gather the c token rows from slots, single EMA write
// No atomics, no seed writes: every output byte written exactly once, every
// input byte read exactly once (533 MB total = the traffic floor).
// Scratch reset folded in race-free (each warp owns its row's count).
//
// Tuning ledger (all empirically closed, both directions where applicable):
//   - register/occupancy frontier: 32regs/72%occ -> 66.7% DRAM (load serial-
//     ization); 40regs/52%occ -> 74.6-75.7% DRAM (PEAK); 84regs/18%occ
//     (row-pair, 8-deep w MLP) -> 66.6% DRAM. 40/6 is the optimum. Do NOT
//     cap regs; do NOT widen per-warp work.
//   - L2 prefetch of w: -1.7us isolated ncu, +2us in graph-replay steady
//     state (rejected twice on timed totals).
//   - PDL overlap of compact: +3.7us launch overhead, no overlap realized.
//   - traffic: at floor; gather-only (R7/R8) and seed+atomic (R4-R6) variants
//     all slower. Streaming/gather co-residency in ONE kernel is the key.
// ---------------------------------------------------------------------------
__global__ void __launch_bounds__(256, 6)
update_kernel(const float4* __restrict__ x4,
              const float4* __restrict__ w4,
              float4* __restrict__ out4) {
    int row  = (blockIdx.x * blockDim.x + threadIdx.x) >> 5;
    int lane = threadIdx.x & 31;

    int c = g_counts[row];                 // uniform across warp
    long base = (long)row * (DIM / 4);

    if (c == 0) {
        float4 a = __ldcs(&w4[base + lane]);
        float4 b = __ldcs(&w4[base + lane + 32]);
        float4 d = __ldcs(&w4[base + lane + 64]);
        float4 e = __ldcs(&w4[base + lane + 96]);
        __stcs(&out4[base + lane],      a);
        __stcs(&out4[base + lane + 32], b);
        __stcs(&out4[base + lane + 64], d);
        __stcs(&out4[base + lane + 96], e);
        return;
    }

    if (lane == 0) g_counts[row] = 0;      // reset for next replay

    // --- gather ranks 0..min(c,K)-1 ---
    float4 s0 = make_float4(0.f, 0.f, 0.f, 0.f);
    float4 s1 = s0, s2 = s0, s3 = s0;

    int ns = (c < K_SLOTS) ? c : K_SLOTS;
    for (int t = 0; t < ns; t++) {
        int tok = g_slot[row * K_SLOTS + t];          // warp-uniform broadcast
        const float4* src = x4 + (long)tok * (DIM / 4);
        float4 a = __ldcs(&src[lane]);
        float4 b = __ldcs(&src[lane + 32]);
        float4 d = __ldcs(&src[lane + 64]);
        float4 e = __ldcs(&src[lane + 96]);
        s0.x += a.x; s0.y += a.y; s0.z += a.z; s0.w += a.w;
        s1.x += b.x; s1.y += b.y; s1.z += b.z; s1.w += b.w;
        s2.x += d.x; s2.y += d.y; s2.z += d.z; s2.w += d.w;
        s3.x += e.x; s3.y += e.y; s3.z += e.z; s3.w += e.w;
    }

    if (c > K_SLOTS) {
        // cold overflow path: correct for any input, never taken for this data
        int remaining = c - K_SLOTS;
        for (int b0 = 0; b0 < S_TOK && remaining > 0; b0 += 32) {
            int vpo = g_ovf_vidp1[b0 + lane];
            unsigned m = __ballot_sync(0xFFFFFFFFu, vpo == row + 1);
            while (m) {
                int j2 = b0 + (__ffs(m) - 1);
                m &= m - 1;
                const float4* src = x4 + (long)j2 * (DIM / 4);
                float4 a = src[lane];
                float4 b = src[lane + 32];
                float4 d = src[lane + 64];
                float4 e = src[lane + 96];
                s0.x += a.x; s0.y += a.y; s0.z += a.z; s0.w += a.w;
                s1.x += b.x; s1.y += b.y; s1.z += b.z; s1.w += b.w;
                s2.x += d.x; s2.y += d.y; s2.z += d.z; s2.w += d.w;
                s3.x += e.x; s3.y += e.y; s3.z += e.z; s3.w += e.w;
                if (lane == 0) g_ovf_vidp1[j2] = 0;   // consume + clear
                remaining--;
            }
        }
    }

    // --- final EMA write ---
    float inv = 0.5f / (float)c;
    float4 w0 = __ldcs(&w4[base + lane]);
    float4 w1 = __ldcs(&w4[base + lane + 32]);
    float4 w2 = __ldcs(&w4[base + lane + 64]);
    float4 w3 = __ldcs(&w4[base + lane + 96]);
    __stcs(&out4[base + lane], make_float4(
        fmaf(s0.x, inv, 0.5f * w0.x), fmaf(s0.y, inv, 0.5f * w0.y),
        fmaf(s0.z, inv, 0.5f * w0.z), fmaf(s0.w, inv, 0.5f * w0.w)));
    __stcs(&out4[base + lane + 32], make_float4(
        fmaf(s1.x, inv, 0.5f * w1.x), fmaf(s1.y, inv, 0.5f * w1.y),
        fmaf(s1.z, inv, 0.5f * w1.z), fmaf(s1.w, inv, 0.5f * w1.w)));
    __stcs(&out4[base + lane + 64], make_float4(
        fmaf(s2.x, inv, 0.5f * w2.x), fmaf(s2.y, inv, 0.5f * w2.y),
        fmaf(s2.z, inv, 0.5f * w2.z), fmaf(s2.w, inv, 0.5f * w2.w)));
    __stcs(&out4[base + lane + 96], make_float4(
        fmaf(s3.x, inv, 0.5f * w3.x), fmaf(s3.y, inv, 0.5f * w3.y),
        fmaf(s3.z, inv, 0.5f * w3.z), fmaf(s3.w, inv, 0.5f * w3.w)));
}

// ---------------------------------------------------------------------------
extern "C" void kernel_launch(void* const* d_in, const int* in_sizes, int n_in,
                              void* d_out, int out_size) {
    const float* out_act   = (const float*)d_in[0];   // [S, D] f32
    const float* l2_weight = (const float*)d_in[1];   // [V, D] f32
    const int*   l2_data   = (const int*)d_in[2];     // [S] i32
    const int*   l2_idxs   = (const int*)d_in[3];     // [S] i32
    float* outp = (float*)d_out;                      // [V, D] f32

    (void)in_sizes; (void)n_in; (void)out_size;

    // 1. histogram + slots (scratch all-zero on entry; 4 tokens/thread,
    //    128-thread blocks -> 256 blocks across 148 SMs)
    compact_kernel<<<S_TOK / 4 / 128, 128>>>((const int4*)l2_data,
                                             (const int4*)l2_idxs);

    // 2. update: c==0 copy + c>=1 gather-EMA + scratch reset (warp-per-row)
    update_kernel<<<VOCAB / 8, 256>>>((const float4*)out_act,
                                      (const float4*)l2_weight,
                                      (float4*)outp);
}